// round 6
// baseline (speedup 1.0000x reference)
#include <cuda_runtime.h>
#include <cuda_bf16.h>
#include <math.h>
#include <stdint.h>

// ---------------- scratch (allocation-free: __device__ globals) ----------------
// split-bf16 pair-packed layout: word kpg of a row = bf16x2 of elements (2*kpg, 2*kpg+1),
// stored at position gidx(kpg) = (kpg & ~15) | ((kpg&3)<<2) | ((kpg>>2)&3)
__device__ __align__(1024) uint32_t g_xs_big[32768ULL * 64];
__device__ __align__(1024) uint32_t g_xs_sml[32768ULL * 64];
__device__ __align__(1024) uint32_t g_h_big[32768ULL * 256];
__device__ __align__(1024) uint32_t g_h_sml[32768ULL * 256];
__device__ __align__(1024) float    g_params[32768ULL * 1792];
__device__ __align__(1024) uint32_t g_w0b[2][512 * 64];
__device__ __align__(1024) uint32_t g_w0s[2][512 * 64];
__device__ __align__(1024) uint32_t g_w1b[2][1792 * 256];
__device__ __align__(1024) uint32_t g_w1s[2][1792 * 256];

#define BVAL   3.0f
#define KBINS  5
#define MIN_BW 0.001f
#define MIN_BH 0.001f
#define MIN_DV 0.001f

// ======================= helpers =======================
__device__ __forceinline__ int gidx(int kpg) {
    return (kpg & ~15) | ((kpg & 3) << 2) | ((kpg >> 2) & 3);
}

__device__ __forceinline__ void split2(float x0, float x1, uint32_t& b, uint32_t& s) {
    __nv_bfloat16 b0 = __float2bfloat16_rn(x0);
    __nv_bfloat16 b1 = __float2bfloat16_rn(x1);
    float r0 = x0 - __bfloat162float(b0);
    float r1 = x1 - __bfloat162float(b1);
    __nv_bfloat16 s0 = __float2bfloat16_rn(r0);
    __nv_bfloat16 s1 = __float2bfloat16_rn(r1);
    b = (uint32_t)__bfloat16_as_ushort(b0) | ((uint32_t)__bfloat16_as_ushort(b1) << 16);
    s = (uint32_t)__bfloat16_as_ushort(s0) | ((uint32_t)__bfloat16_as_ushort(s1) << 16);
}

__device__ __forceinline__ void mma_bf16(float* d,
                                         uint32_t a0, uint32_t a1, uint32_t a2, uint32_t a3,
                                         uint32_t b0, uint32_t b1) {
    asm volatile(
        "mma.sync.aligned.m16n8k16.row.col.f32.bf16.bf16.f32 "
        "{%0,%1,%2,%3}, {%4,%5,%6,%7}, {%8,%9}, {%0,%1,%2,%3};"
        : "+f"(d[0]), "+f"(d[1]), "+f"(d[2]), "+f"(d[3])
        : "r"(a0), "r"(a1), "r"(a2), "r"(a3), "r"(b0), "r"(b1));
}

#define CP16(dst, src) \
    asm volatile("cp.async.cg.shared.global [%0], [%1], 16;" :: "r"(dst), "l"(src) : "memory")
#define CP_COMMIT() asm volatile("cp.async.commit_group;" ::: "memory")
#define CP_WAIT1()  asm volatile("cp.async.wait_group 1;" ::: "memory")
#define CP_WAIT0()  asm volatile("cp.async.wait_group 0;" ::: "memory")

__device__ __forceinline__ uint32_t smem_u32(const void* p) {
    uint32_t a;
    asm("{ .reg .u64 t; cvta.to.shared.u64 t, %1; cvt.u32.u64 %0, t; }" : "=r"(a) : "l"(p));
    return a;
}

// ======================= converters =======================
__global__ void __launch_bounds__(256) conv_x(const float* __restrict__ x, int xoff,
                                              uint32_t* __restrict__ ob,
                                              uint32_t* __restrict__ os) {
    int t = blockIdx.x * 256 + threadIdx.x;
    int row = t >> 6, kpg = t & 63;
    float2 v = *(const float2*)(x + (size_t)row * 256 + xoff + 2 * kpg);
    uint32_t b, s;
    split2(v.x, v.y, b, s);
    int dst = row * 64 + gidx(kpg);
    ob[dst] = b; os[dst] = s;
}

__global__ void __launch_bounds__(256) conv_w(const float* __restrict__ w, int M, int K2,
                                              uint32_t* __restrict__ ob,
                                              uint32_t* __restrict__ os) {
    __shared__ uint32_t tb[32][33], ts[32][33];
    const int m0 = blockIdx.x * 32, kp0 = blockIdx.y * 32;
    const int xx = threadIdx.x, yy = threadIdx.y;
    for (int i = yy; i < 32; i += 8) {
        int kpg = kp0 + i, m = m0 + xx;
        float v0 = w[(size_t)(2 * kpg) * M + m];
        float v1 = w[(size_t)(2 * kpg + 1) * M + m];
        split2(v0, v1, tb[i][xx], ts[i][xx]);
    }
    __syncthreads();
    for (int i = yy; i < 32; i += 8) {
        int m = m0 + i;
        size_t dst = (size_t)m * K2 + gidx(kp0 + xx);
        ob[dst] = tb[xx][i]; os[dst] = ts[xx][i];
    }
}

// ======================= bf16x3 tensor-core GEMM =======================
// 3-stage cp.async pipeline, ONE __syncthreads per mainloop iteration.
// Block tile 128x128 (BK = 16 words = 32 k), 256 threads (8 warps 2x4), warp 64x32.
// stage layout (words): Ab 0, As 2048, Bb 4096, Bs 6144; stage stride 8192 words.
#define GEMM_SMEM (3 * 32768)

template <int EPI>
__global__ void __launch_bounds__(256, 2) gemm_bf16x3(
    const uint32_t* __restrict__ Ab, const uint32_t* __restrict__ As,
    const uint32_t* __restrict__ Bb, const uint32_t* __restrict__ Bs,
    const float* __restrict__ bias,
    float* __restrict__ C, uint32_t* __restrict__ Hb, uint32_t* __restrict__ Hs,
    int M, int K2)
{
    extern __shared__ uint32_t sm[];
    const uint32_t sbase = smem_u32(sm);
    const int tid  = threadIdx.x;
    const int lane = tid & 31;
    const int wid  = tid >> 5;
    const int warp_m = wid & 1;
    const int warp_n = wid >> 1;
    const int rowBase = blockIdx.y * 128;
    const int colBase = blockIdx.x * 128;
    const int q  = lane & 3;
    const int rw = lane >> 2;

    const int cr  = tid >> 1;
    const int cw8 = (tid & 1) * 8;
    const uint32_t* gAb = Ab + (size_t)(rowBase + cr) * K2 + cw8;
    const uint32_t* gAs = As + (size_t)(rowBase + cr) * K2 + cw8;
    const uint32_t* gBb = Bb + (size_t)(colBase + cr) * K2 + cw8;
    const uint32_t* gBs = Bs + (size_t)(colBase + cr) * K2 + cw8;
    const uint32_t sdst = sbase + (uint32_t)(cr * 16 + cw8) * 4;

#define STAGE(it, buf) do { \
        uint32_t d0 = sdst + (uint32_t)(buf) * 32768u; \
        const uint32_t* pa = gAb + (it) * 16; \
        const uint32_t* ps = gAs + (it) * 16; \
        const uint32_t* pb = gBb + (it) * 16; \
        const uint32_t* pq = gBs + (it) * 16; \
        CP16(d0,          pa); CP16(d0 + 16,          pa + 4); \
        CP16(d0 + 8192,   ps); CP16(d0 + 8192 + 16,   ps + 4); \
        CP16(d0 + 16384,  pb); CP16(d0 + 16384 + 16,  pb + 4); \
        CP16(d0 + 24576,  pq); CP16(d0 + 24576 + 16,  pq + 4); \
        CP_COMMIT(); \
    } while (0)

    float acc[4][4][4];
#pragma unroll
    for (int mt = 0; mt < 4; mt++)
#pragma unroll
        for (int nt = 0; nt < 4; nt++)
#pragma unroll
            for (int c = 0; c < 4; c++) acc[mt][nt][c] = 0.f;

    const int nIter = K2 >> 4;
    STAGE(0, 0);
    STAGE(1, 1);

    int buf = 0;
    for (int it = 0; it < nIter; it++) {
        if (it + 1 < nIter) { CP_WAIT1(); } else { CP_WAIT0(); }
        __syncthreads();
        if (it + 2 < nIter) {
            int nb = buf + 2; if (nb >= 3) nb -= 3;
            STAGE(it + 2, nb);
        }

        const uint32_t* sA = sm + buf * 8192;
        const uint32_t* sB = sA + 4096;

        uint4 bbig[4], bsml[4];
#pragma unroll
        for (int nt = 0; nt < 4; nt++) {
            const uint32_t* p = sB + (warp_n * 32 + nt * 8 + rw) * 16 + 4 * q;
            bbig[nt] = *(const uint4*)p;
            bsml[nt] = *(const uint4*)(p + 2048);
        }

#pragma unroll
        for (int mt = 0; mt < 4; mt++) {
            const uint32_t* p = sA + (warp_m * 64 + mt * 16 + rw) * 16 + 4 * q;
            uint4 alo = *(const uint4*)p;
            uint4 ahi = *(const uint4*)(p + 128);
            uint4 slo = *(const uint4*)(p + 2048);
            uint4 shi = *(const uint4*)(p + 2048 + 128);
#pragma unroll
            for (int nt = 0; nt < 4; nt++)
                mma_bf16(acc[mt][nt], alo.x, ahi.x, alo.y, ahi.y, bbig[nt].x, bbig[nt].y);
#pragma unroll
            for (int nt = 0; nt < 4; nt++)
                mma_bf16(acc[mt][nt], alo.z, ahi.z, alo.w, ahi.w, bbig[nt].z, bbig[nt].w);
#pragma unroll
            for (int nt = 0; nt < 4; nt++)
                mma_bf16(acc[mt][nt], slo.x, shi.x, slo.y, shi.y, bbig[nt].x, bbig[nt].y);
#pragma unroll
            for (int nt = 0; nt < 4; nt++)
                mma_bf16(acc[mt][nt], slo.z, shi.z, slo.w, shi.w, bbig[nt].z, bbig[nt].w);
#pragma unroll
            for (int nt = 0; nt < 4; nt++)
                mma_bf16(acc[mt][nt], alo.x, ahi.x, alo.y, ahi.y, bsml[nt].x, bsml[nt].y);
#pragma unroll
            for (int nt = 0; nt < 4; nt++)
                mma_bf16(acc[mt][nt], alo.z, ahi.z, alo.w, ahi.w, bsml[nt].z, bsml[nt].w);
        }
        buf++; if (buf >= 3) buf -= 3;
    }

    // ---- epilogue ----
#pragma unroll
    for (int mt = 0; mt < 4; mt++) {
#pragma unroll
        for (int nt = 0; nt < 4; nt++) {
            int row = rowBase + warp_m * 64 + mt * 16 + rw;
            int col = colBase + warp_n * 32 + nt * 8 + q * 2;
            float b0 = bias[col], b1 = bias[col + 1];
            float v0 = acc[mt][nt][0] + b0, v1 = acc[mt][nt][1] + b1;
            float v2 = acc[mt][nt][2] + b0, v3 = acc[mt][nt][3] + b1;
            if (EPI == 1) {
                v0 = tanhf(v0); v1 = tanhf(v1); v2 = tanhf(v2); v3 = tanhf(v3);
                int dcol = gidx(col >> 1);
                uint32_t bb, ss;
                split2(v0, v1, bb, ss);
                Hb[(size_t)row * (M >> 1) + dcol] = bb;
                Hs[(size_t)row * (M >> 1) + dcol] = ss;
                split2(v2, v3, bb, ss);
                Hb[(size_t)(row + 8) * (M >> 1) + dcol] = bb;
                Hs[(size_t)(row + 8) * (M >> 1) + dcol] = ss;
            } else {
                *(float2*)&C[(size_t)row * M + col]       = make_float2(v0, v1);
                *(float2*)&C[(size_t)(row + 8) * M + col] = make_float2(v2, v3);
            }
        }
    }
#undef STAGE
}

// ======================= spline =======================
__device__ __forceinline__ float softplusf(float x) {
    return (x > 20.0f) ? x : log1pf(expf(x));
}

__global__ void __launch_bounds__(128) spline_kernel(
    const float* __restrict__ xin, int xoff,
    const float* __restrict__ params,
    float* __restrict__ z, int zoff,
    float* __restrict__ logdet, int add)
{
    const int n = blockIdx.x;
    const int d = threadIdx.x;

    // coalesced staged load of this row's 1792 params
    __shared__ float ps[1792];
    {
        const float4* src = (const float4*)(params + (size_t)n * 1792);
#pragma unroll
        for (int i = 0; i < 3; i++)
            *(float4*)&ps[(d + i * 128) * 4] = src[d + i * 128];
        if (d < 64) *(float4*)&ps[(d + 384) * 4] = src[d + 384];
    }
    __syncthreads();

    float raw[14];
#pragma unroll
    for (int j = 0; j < 14; j++) raw[j] = ps[d * 14 + j];

    const float t = xin[(size_t)n * 256 + xoff + d];

    float cw[6], wd[5];
    {
        float m = raw[0];
#pragma unroll
        for (int j = 1; j < 5; j++) m = fmaxf(m, raw[j]);
        float e[5], s = 0.f;
#pragma unroll
        for (int j = 0; j < 5; j++) { e[j] = expf(raw[j] - m); s += e[j]; }
        float Wu[5];
#pragma unroll
        for (int j = 0; j < 5; j++) Wu[j] = 2.0f * BVAL * e[j] / s;
        float m2 = Wu[0];
#pragma unroll
        for (int j = 1; j < 5; j++) m2 = fmaxf(m2, Wu[j]);
        float e2[5], s2 = 0.f;
#pragma unroll
        for (int j = 0; j < 5; j++) { e2[j] = expf(Wu[j] - m2); s2 += e2[j]; }
        cw[0] = -BVAL;
        float run = 0.f;
#pragma unroll
        for (int j = 0; j < 5; j++) {
            float w = MIN_BW + (1.0f - MIN_BW * KBINS) * (e2[j] / s2);
            run += w;
            cw[j + 1] = 2.0f * BVAL * run - BVAL;
        }
        cw[5] = BVAL;
#pragma unroll
        for (int j = 0; j < 5; j++) wd[j] = cw[j + 1] - cw[j];
    }

    float ch[6], hd[5];
    {
        float m = raw[5];
#pragma unroll
        for (int j = 1; j < 5; j++) m = fmaxf(m, raw[5 + j]);
        float e[5], s = 0.f;
#pragma unroll
        for (int j = 0; j < 5; j++) { e[j] = expf(raw[5 + j] - m); s += e[j]; }
        float Hu[5];
#pragma unroll
        for (int j = 0; j < 5; j++) Hu[j] = 2.0f * BVAL * e[j] / s;
        float m2 = Hu[0];
#pragma unroll
        for (int j = 1; j < 5; j++) m2 = fmaxf(m2, Hu[j]);
        float e2[5], s2 = 0.f;
#pragma unroll
        for (int j = 0; j < 5; j++) { e2[j] = expf(Hu[j] - m2); s2 += e2[j]; }
        ch[0] = -BVAL;
        float run = 0.f;
#pragma unroll
        for (int j = 0; j < 5; j++) {
            float h = MIN_BH + (1.0f - MIN_BH * KBINS) * (e2[j] / s2);
            run += h;
            ch[j + 1] = 2.0f * BVAL * run - BVAL;
        }
        ch[5] = BVAL;
#pragma unroll
        for (int j = 0; j < 5; j++) hd[j] = ch[j + 1] - ch[j];
    }

    float deriv[6];
    deriv[0] = 1.0f;
    deriv[5] = 1.0f;
#pragma unroll
    for (int j = 0; j < 4; j++) {
        float du = softplusf(raw[10 + j]);
        deriv[j + 1] = MIN_DV + softplusf(du);
    }

    const float xc = fminf(fmaxf(t, -BVAL), BVAL);
    int cnt = 0;
#pragma unroll
    for (int j = 0; j < 6; j++) cnt += (xc >= cw[j]) ? 1 : 0;
    int idx = min(max(cnt - 1, 0), 4);

    const float icw = cw[idx], iw = wd[idx];
    const float ich = ch[idx], ih = hd[idx];
    const float delta = ih / iw;
    const float dk = deriv[idx], dk1 = deriv[idx + 1];
    const float theta = (xc - icw) / iw;
    const float t1m = theta * (1.0f - theta);
    const float num = ih * (delta * theta * theta + dk * t1m);
    const float den = delta + (dk + dk1 - 2.0f * delta) * t1m;
    const float y = ich + num / den;
    const float omt = 1.0f - theta;
    const float dnum = delta * delta * (dk1 * theta * theta + 2.0f * delta * t1m + dk * omt * omt);
    const float ld = logf(dnum) - 2.0f * logf(den);

    const bool inside = (t >= -BVAL) && (t <= BVAL);
    const float outv = inside ? y : t;
    const float ldv  = inside ? ld : 0.0f;

    z[(size_t)n * 256 + zoff + d] = outv;

    __shared__ float red[128];
    red[d] = ldv;
    __syncthreads();
#pragma unroll
    for (int s = 64; s > 0; s >>= 1) {
        if (d < s) red[d] += red[d + s];
        __syncthreads();
    }
    if (d == 0) {
        if (add) logdet[n] += red[0];
        else     logdet[n]  = red[0];
    }
}

// ======================= host side =======================
extern "C" void kernel_launch(void* const* d_in, const int* in_sizes, int n_in,
                              void* d_out, int out_size)
{
    const float* x     = (const float*)d_in[0];
    const float* f0_w0 = (const float*)d_in[1];
    const float* f0_b0 = (const float*)d_in[2];
    const float* f0_w1 = (const float*)d_in[3];
    const float* f0_b1 = (const float*)d_in[4];
    const float* f1_w0 = (const float*)d_in[5];
    const float* f1_b0 = (const float*)d_in[6];
    const float* f1_w1 = (const float*)d_in[7];
    const float* f1_b1 = (const float*)d_in[8];

    const int N = in_sizes[0] / 256;              // 32768
    float* z      = (float*)d_out;
    float* logdet = z + (size_t)N * 256;

    uint32_t *xsb, *xss, *hb, *hs, *w0b, *w0s, *w1b, *w1s;
    float* params;
    cudaGetSymbolAddress((void**)&xsb, g_xs_big);
    cudaGetSymbolAddress((void**)&xss, g_xs_sml);
    cudaGetSymbolAddress((void**)&hb,  g_h_big);
    cudaGetSymbolAddress((void**)&hs,  g_h_sml);
    cudaGetSymbolAddress((void**)&params, g_params);
    cudaGetSymbolAddress((void**)&w0b, g_w0b);
    cudaGetSymbolAddress((void**)&w0s, g_w0s);
    cudaGetSymbolAddress((void**)&w1b, g_w1b);
    cudaGetSymbolAddress((void**)&w1s, g_w1s);

    cudaFuncSetAttribute(gemm_bf16x3<0>, cudaFuncAttributeMaxDynamicSharedMemorySize, GEMM_SMEM);
    cudaFuncSetAttribute(gemm_bf16x3<1>, cudaFuncAttributeMaxDynamicSharedMemorySize, GEMM_SMEM);

    const dim3 tw(32, 8);
    const dim3 g1(512 / 128, N / 128);
    const dim3 g2(1792 / 128, N / 128);
    const int nConvBlocks = N * 64 / 256;

    // launch order arranged so ncu -s 5 -c 1 captures the BIG gemm (launch #6)
    conv_w<<<dim3(512 / 32, 64 / 32), tw>>>(f0_w0, 512, 64, w0b, w0s);                       // 1
    conv_w<<<dim3(1792 / 32, 256 / 32), tw>>>(f0_w1, 1792, 256, w1b, w1s);                   // 2
    conv_w<<<dim3(512 / 32, 64 / 32), tw>>>(f1_w0, 512, 64, w0b + 512 * 64, w0s + 512 * 64); // 3
    conv_x<<<nConvBlocks, 256>>>(x, 0, xsb, xss);                                            // 4
    gemm_bf16x3<1><<<g1, 256, GEMM_SMEM>>>(xsb, xss, w0b, w0s, f0_b0,
                                           nullptr, hb, hs, 512, 64);                        // 5
    gemm_bf16x3<0><<<g2, 256, GEMM_SMEM>>>(hb, hs, w1b, w1s, f0_b1,
                                           params, nullptr, nullptr, 1792, 256);             // 6 <- profiled
    spline_kernel<<<N, 128>>>(x, 128, params, z, 128, logdet, 0);                            // 7
    conv_w<<<dim3(1792 / 32, 256 / 32), tw>>>(f1_w1, 1792, 256,
                                              w1b + 1792 * 256, w1s + 1792 * 256);           // 8
    conv_x<<<nConvBlocks, 256>>>(z, 128, xsb, xss);                                          // 9
    gemm_bf16x3<1><<<g1, 256, GEMM_SMEM>>>(xsb, xss, w0b + 512 * 64, w0s + 512 * 64, f1_b0,
                                           nullptr, hb, hs, 512, 64);                        // 10
    gemm_bf16x3<0><<<g2, 256, GEMM_SMEM>>>(hb, hs, w1b + 1792 * 256, w1s + 1792 * 256, f1_b1,
                                           params, nullptr, nullptr, 1792, 256);             // 11
    spline_kernel<<<N, 128>>>(x, 0, params, z, 0, logdet, 1);                                // 12
}